// round 5
// baseline (speedup 1.0000x reference)
#include <cuda_runtime.h>

#define IMG   64
#define CH    16
#define B     8
#define N_PIX 4096   // 64*64

// ---------------- scratch (no allocations allowed) ----------------
__device__ float g_buf0[B * CH * N_PIX];
__device__ float g_buf1[B * CH * N_PIX];
__device__ float g_xc  [B * CH * N_PIX];
__device__ float g_invs[B * N_PIX];

// packed conv weights, pair = {w[2*ocp], w[2*ocp+1]} for (ic,ky,kx)
__device__ unsigned long long g_w1pa[8 * 16 * 5 * 4];
__device__ unsigned long long g_w1pb[8 * 16 * 5];
__device__ unsigned long long g_w2pa[8 * 16 * 5 * 4];
__device__ unsigned long long g_w2pb[8 * 16 * 5];
__device__ unsigned long long g_b1p[8];
__device__ unsigned long long g_b2p[8];

#define FMA2(acc, a, b)  asm("fma.rn.f32x2 %0, %1, %2, %0;" : "+l"(acc) : "l"(a), "l"(b))
#define ADD2(acc, a)     asm("add.rn.f32x2 %0, %0, %1;" : "+l"(acc) : "l"(a))
#define DUP2(p, v)       asm("mov.b64 %0, {%1, %1};" : "=l"(p) : "f"(v))
#define PACK2(p, lo, hi) asm("mov.b64 %0, {%1, %2};" : "=l"(p) : "f"(lo), "f"(hi))
#define UNPK2(lo, hi, p) asm("mov.b64 {%0, %1}, %2;" : "=f"(lo), "=f"(hi) : "l"(p))
#define STG_CS4(ptr, a, b, c, d) \
    asm volatile("st.global.cs.v4.f32 [%0], {%1, %2, %3, %4};" \
                 :: "l"(ptr), "f"(a), "f"(b), "f"(c), "f"(d))

// ---------------- conv0 (1->16ch) + weight-pair packing fused ----------------
__global__ void conv0_kernel(const float* __restrict__ x,
                             const float* __restrict__ w,
                             const float* __restrict__ bias,
                             const float* __restrict__ w1, const float* __restrict__ b1,
                             const float* __restrict__ w2, const float* __restrict__ b2) {
    int id = blockIdx.x * blockDim.x + threadIdx.x;

    if (blockIdx.x < 26) {
        int idx = id;
        if (idx < 6400) {
            int which = idx >= 3200;
            int r = which ? idx - 3200 : idx;
            int kx = r % 5;
            int g  = r / 5;
            int ocic = g / 5;
            int ic  = ocic & 15;
            int ocp = ocic >> 4;
            int ky  = g % 5;
            const float* wsrc = which ? w2 : w1;
            float lo = wsrc[(2 * ocp) * 400 + ic * 25 + ky * 5 + kx];
            float hi = wsrc[(2 * ocp + 1) * 400 + ic * 25 + ky * 5 + kx];
            unsigned long long p;
            PACK2(p, lo, hi);
            if (kx < 4) { (which ? g_w2pa : g_w1pa)[g * 4 + kx] = p; }
            else        { (which ? g_w2pb : g_w1pb)[g]          = p; }
        } else if (idx < 6416) {
            int k = idx - 6400;
            int which = k >= 8;
            int p = k & 7;
            const float* bb = which ? b2 : b1;
            unsigned long long pr;
            PACK2(pr, bb[2 * p], bb[2 * p + 1]);
            (which ? g_b2p : g_b1p)[p] = pr;
        }
    }

    int pix = id & 4095;
    int oc  = (id >> 12) & 15;
    int b   = id >> 16;
    int py = pix >> 6, px = pix & 63;
    const float* xin = x + b * N_PIX;
    float acc = __ldg(bias + oc);
    #pragma unroll
    for (int ky = 0; ky < 5; ky++) {
        int gy = py + ky - 2;
        if (gy < 0 || gy >= IMG) continue;
        #pragma unroll
        for (int kx = 0; kx < 5; kx++) {
            int gx = px + kx - 2;
            if (gx < 0 || gx >= IMG) continue;
            acc = fmaf(xin[gy * IMG + gx], __ldg(w + oc * 25 + ky * 5 + kx), acc);
        }
    }
    g_buf0[id] = acc;
}

// ---------------- conv16 split: 512 threads = 4 ic-groups x (32x4 tile) ----------------
template<bool FUSE>
__global__ void __launch_bounds__(512) conv16s_kernel() {
    __shared__ __align__(16) char smraw[44032];
    float* sin_t            = (float*)smraw;                         // 18432 B
    unsigned long long* swa = (unsigned long long*)(smraw + 18432);  // 20480 B
    unsigned long long* swb = (unsigned long long*)(smraw + 38912);  //  5120 B
    unsigned long long* sred = (unsigned long long*)(smraw + 18432); // overlay

    const float* in = FUSE ? g_buf1 : g_buf0;
    const unsigned long long* gwa = FUSE ? g_w2pa : g_w1pa;
    const unsigned long long* gwb = FUSE ? g_w2pb : g_w1pb;
    const unsigned long long* gbp = FUSE ? g_b2p  : g_b1p;

    int tid  = threadIdx.x;
    int tile = blockIdx.x;
    int b    = blockIdx.y;
    int tx0  = (tile & 1) * 32;
    int ty0  = (tile >> 1) * 4;

    for (int i = tid; i < 8 * 16 * 5 * 4; i += 512) swa[i] = gwa[i];
    for (int i = tid; i < 8 * 16 * 5;     i += 512) swb[i] = gwb[i];

    const float* inb = in + b * CH * N_PIX;
    for (int idx = tid; idx < CH * 8 * 36; idx += 512) {
        int c   = idx / 288;
        int rem = idx - c * 288;
        int r   = rem / 36;
        int cc  = rem - r * 36;
        int gy = ty0 + r - 2;
        int gx = tx0 + cc - 2;
        float v = 0.f;
        if (gy >= 0 && gy < IMG && gx >= 0 && gx < IMG)
            v = inb[c * N_PIX + gy * IMG + gx];
        sin_t[idx] = v;
    }
    __syncthreads();

    int grp = tid >> 7;
    int wg  = tid & 127;
    int tx = wg & 31, ty = wg >> 5;

    unsigned long long acc[8];
    #pragma unroll
    for (int p = 0; p < 8; p++) acc[p] = 0ULL;

    #pragma unroll
    for (int icl = 0; icl < 4; icl++) {
        int ic = grp * 4 + icl;
        const float* srow = &sin_t[ic * 288 + ty * 36 + tx];
        #pragma unroll
        for (int ky = 0; ky < 5; ky++) {
            const float* rr = srow + ky * 36;
            unsigned long long pa0, pa1, pa2, pa3, pa4;
            DUP2(pa0, rr[0]); DUP2(pa1, rr[1]); DUP2(pa2, rr[2]);
            DUP2(pa3, rr[3]); DUP2(pa4, rr[4]);
            #pragma unroll
            for (int p = 0; p < 8; p++) {
                int g = (p * 16 + ic) * 5 + ky;
                const ulonglong2* wq = reinterpret_cast<const ulonglong2*>(&swa[g * 4]);
                ulonglong2 q0 = wq[0];
                ulonglong2 q1 = wq[1];
                unsigned long long w4 = swb[g];
                FMA2(acc[p], pa0, q0.x);
                FMA2(acc[p], pa1, q0.y);
                FMA2(acc[p], pa2, q1.x);
                FMA2(acc[p], pa3, q1.y);
                FMA2(acc[p], pa4, w4);
            }
        }
    }

    __syncthreads();
    if (grp > 0) {
        #pragma unroll
        for (int p = 0; p < 8; p++)
            sred[p * 384 + (grp - 1) * 128 + wg] = acc[p];
    }
    __syncthreads();

    if (grp == 0) {
        #pragma unroll
        for (int p = 0; p < 8; p++) {
            ADD2(acc[p], sred[p * 384 + wg]);
            ADD2(acc[p], sred[p * 384 + 128 + wg]);
            ADD2(acc[p], sred[p * 384 + 256 + wg]);
            ADD2(acc[p], gbp[p]);
        }

        int py = ty0 + ty, px = tx0 + tx;
        int pix = py * IMG + px;

        if (!FUSE) {
            float* outb = g_buf1 + b * CH * N_PIX + pix;
            #pragma unroll
            for (int p = 0; p < 8; p++) {
                float lo, hi;
                UNPK2(lo, hi, acc[p]);
                outb[(2 * p) * N_PIX]     = lo;
                outb[(2 * p + 1) * N_PIX] = hi;
            }
        } else {
            float v[16];
            float s = 0.f;
            #pragma unroll
            for (int p = 0; p < 8; p++) {
                UNPK2(v[2 * p], v[2 * p + 1], acc[p]);
                s += v[2 * p] + v[2 * p + 1];
            }
            float mean = s * (1.f / 16.f);
            float var = 0.f;
            float* xcb = g_xc + b * CH * N_PIX + pix;
            #pragma unroll
            for (int c = 0; c < 16; c++) {
                float d = v[c] - mean;
                var = fmaf(d, d, var);
                xcb[c * N_PIX] = d;
            }
            var *= (1.f / 15.f);
            g_invs[b * N_PIX + pix] = rsqrtf(var);
        }
    }
}

// ---------------- coupling v2: 64 threads, 8x8 per-thread tile, register-transpose mirror ----------------
// out[b,i,j] = (xc_i . xc_j)/16 * s_i * s_j * mask. Symmetric pairs only (tj >= ti);
// mirror tile stored directly from registers (square per-thread tile => transpose is free).
__global__ void __launch_bounds__(64) coupling_kernel(const float* __restrict__ mask,
                                                      float* __restrict__ out) {
    __shared__ __align__(16) float sxi[16 * 64];
    __shared__ __align__(16) float sxj[16 * 64];
    __shared__ float sii[64];
    __shared__ float sij[64];

    int b = blockIdx.x;             // batch fastest -> mask tiles reused in L2 across batches
    int p = blockIdx.y;             // 0..2079 triangular pair index (T=64)

    int ti = (int)((129.0f - sqrtf(129.0f * 129.0f - 8.0f * (float)p)) * 0.5f);
    while (((ti + 1) * 64 - ((ti + 1) * ti) / 2) <= p) ti++;
    while ((ti * 64 - (ti * (ti - 1)) / 2) > p) ti--;
    int tj = ti + (p - (ti * 64 - (ti * (ti - 1)) / 2));
    bool diag = (ti == tj);

    int tid = threadIdx.x;
    const float* xcb = g_xc + b * CH * N_PIX;

    // fill sxi/sxj (16x64 each) with float4 loads
    #pragma unroll
    for (int it = 0; it < 8; it++) {
        int i = it * 64 + tid;            // 0..511
        int which = i >> 8;               // 0: sxi, 1: sxj
        int k = i & 255;                  // float4 index within tile
        int c = k >> 4;
        int q = k & 15;
        int t0 = which ? tj : ti;
        float4 v = *reinterpret_cast<const float4*>(xcb + c * N_PIX + t0 * 64 + q * 4);
        (which ? reinterpret_cast<float4*>(sxj) : reinterpret_cast<float4*>(sxi))[k] = v;
    }
    sii[tid] = g_invs[b * N_PIX + ti * 64 + tid];
    sij[tid] = g_invs[b * N_PIX + tj * 64 + tid];
    __syncthreads();

    int txj = tid & 7, tyi = tid >> 3;
    int jl = txj * 8, il = tyi * 8;

    unsigned long long acc[32];           // acc[ii*4 + p], p = j-pair index
    #pragma unroll
    for (int k = 0; k < 32; k++) acc[k] = 0ULL;

    #pragma unroll
    for (int c = 0; c < 16; c++) {
        const float4* ap = reinterpret_cast<const float4*>(&sxi[c * 64 + il]);
        float4 a0 = ap[0], a1 = ap[1];
        const ulonglong2* bp = reinterpret_cast<const ulonglong2*>(&sxj[c * 64 + jl]);
        ulonglong2 b0 = bp[0], b1 = bp[1];
        float av[8] = {a0.x, a0.y, a0.z, a0.w, a1.x, a1.y, a1.z, a1.w};
        #pragma unroll
        for (int ii = 0; ii < 8; ii++) {
            unsigned long long pa;
            DUP2(pa, av[ii]);
            FMA2(acc[ii * 4 + 0], pa, b0.x);
            FMA2(acc[ii * 4 + 1], pa, b0.y);
            FMA2(acc[ii * 4 + 2], pa, b1.x);
            FMA2(acc[ii * 4 + 3], pa, b1.y);
        }
    }

    // scale: v[ii][jj] = acc * s_i * s_j / 16
    float sj[8];
    #pragma unroll
    for (int jj = 0; jj < 8; jj++) sj[jj] = sij[jl + jj];

    float v[8][8];
    #pragma unroll
    for (int ii = 0; ii < 8; ii++) {
        float si = sii[il + ii] * 0.0625f;
        #pragma unroll
        for (int pp = 0; pp < 4; pp++)
            UNPK2(v[ii][2 * pp], v[ii][2 * pp + 1], acc[ii * 4 + pp]);
        #pragma unroll
        for (int jj = 0; jj < 8; jj++)
            v[ii][jj] *= si * sj[jj];
    }

    size_t obase = (size_t)b * N_PIX * N_PIX;

    // forward tile: rows ig, cols jg (coalesced along j)
    #pragma unroll
    for (int ii = 0; ii < 8; ii++) {
        int ig = ti * 64 + il + ii;
        const float* mrow = mask + (size_t)ig * N_PIX + tj * 64 + jl;
        float4 m0 = *reinterpret_cast<const float4*>(mrow);
        float4 m1 = *reinterpret_cast<const float4*>(mrow + 4);
        float* orow = out + obase + (size_t)ig * N_PIX + tj * 64 + jl;
        STG_CS4(orow,     v[ii][0] * m0.x, v[ii][1] * m0.y, v[ii][2] * m0.z, v[ii][3] * m0.w);
        STG_CS4(orow + 4, v[ii][4] * m1.x, v[ii][5] * m1.y, v[ii][6] * m1.z, v[ii][7] * m1.w);
    }

    // mirror tile: rows jg, cols ig — same registers, roles swapped (free transpose)
    if (!diag) {
        #pragma unroll
        for (int jj = 0; jj < 8; jj++) {
            int jg = tj * 64 + jl + jj;
            const float* mrow = mask + (size_t)jg * N_PIX + ti * 64 + il;
            float4 m0 = *reinterpret_cast<const float4*>(mrow);
            float4 m1 = *reinterpret_cast<const float4*>(mrow + 4);
            float* orow = out + obase + (size_t)jg * N_PIX + ti * 64 + il;
            STG_CS4(orow,     v[0][jj] * m0.x, v[1][jj] * m0.y, v[2][jj] * m0.z, v[3][jj] * m0.w);
            STG_CS4(orow + 4, v[4][jj] * m1.x, v[5][jj] * m1.y, v[6][jj] * m1.z, v[7][jj] * m1.w);
        }
    }
}

// ---------------- launch ----------------
extern "C" void kernel_launch(void* const* d_in, const int* in_sizes, int n_in,
                              void* d_out, int out_size) {
    const float* x    = (const float*)d_in[0];
    const float* w0   = (const float*)d_in[1];
    const float* b0   = (const float*)d_in[2];
    const float* w1   = (const float*)d_in[3];
    const float* b1   = (const float*)d_in[4];
    const float* w2   = (const float*)d_in[5];
    const float* b2   = (const float*)d_in[6];
    const float* mask = (const float*)d_in[7];
    float* out = (float*)d_out;

    conv0_kernel<<<(B * CH * N_PIX) / 256, 256>>>(x, w0, b0, w1, b1, w2, b2);
    conv16s_kernel<false><<<dim3(32, B), 512>>>();      // g_buf0 -> g_buf1
    conv16s_kernel<true ><<<dim3(32, B), 512>>>();      // g_buf1 -> g_xc, g_invs
    coupling_kernel<<<dim3(B, 2080), 64>>>(mask, out);  // -> d_out
}

// round 6
// speedup vs baseline: 1.3675x; 1.3675x over previous
#include <cuda_runtime.h>

#define IMG   64
#define CH    16
#define B     8
#define N_PIX 4096   // 64*64

// ---------------- scratch (no allocations allowed) ----------------
__device__ float g_buf0[B * CH * N_PIX];
__device__ float g_buf1[B * CH * N_PIX];
__device__ float g_xc  [B * CH * N_PIX];
__device__ float g_invs[B * N_PIX];

// packed conv weights, pair = {w[2*ocp], w[2*ocp+1]} for (ic,ky,kx)
__device__ unsigned long long g_w1pa[8 * 16 * 5 * 4];
__device__ unsigned long long g_w1pb[8 * 16 * 5];
__device__ unsigned long long g_w2pa[8 * 16 * 5 * 4];
__device__ unsigned long long g_w2pb[8 * 16 * 5];
__device__ unsigned long long g_b1p[8];
__device__ unsigned long long g_b2p[8];

#define FMA2(acc, a, b)  asm("fma.rn.f32x2 %0, %1, %2, %0;" : "+l"(acc) : "l"(a), "l"(b))
#define ADD2(acc, a)     asm("add.rn.f32x2 %0, %0, %1;" : "+l"(acc) : "l"(a))
#define DUP2(p, v)       asm("mov.b64 %0, {%1, %1};" : "=l"(p) : "f"(v))
#define PACK2(p, lo, hi) asm("mov.b64 %0, {%1, %2};" : "=l"(p) : "f"(lo), "f"(hi))
#define UNPK2(lo, hi, p) asm("mov.b64 {%0, %1}, %2;" : "=f"(lo), "=f"(hi) : "l"(p))
#define STG_CS4(ptr, a, b, c, d) \
    asm volatile("st.global.cs.v4.f32 [%0], {%1, %2, %3, %4};" \
                 :: "l"(ptr), "f"(a), "f"(b), "f"(c), "f"(d))

// ---------------- conv0 (1->16ch) + weight-pair packing fused ----------------
__global__ void conv0_kernel(const float* __restrict__ x,
                             const float* __restrict__ w,
                             const float* __restrict__ bias,
                             const float* __restrict__ w1, const float* __restrict__ b1,
                             const float* __restrict__ w2, const float* __restrict__ b2) {
    int id = blockIdx.x * blockDim.x + threadIdx.x;

    if (blockIdx.x < 26) {
        int idx = id;
        if (idx < 6400) {
            int which = idx >= 3200;
            int r = which ? idx - 3200 : idx;
            int kx = r % 5;
            int g  = r / 5;
            int ocic = g / 5;
            int ic  = ocic & 15;
            int ocp = ocic >> 4;
            int ky  = g % 5;
            const float* wsrc = which ? w2 : w1;
            float lo = wsrc[(2 * ocp) * 400 + ic * 25 + ky * 5 + kx];
            float hi = wsrc[(2 * ocp + 1) * 400 + ic * 25 + ky * 5 + kx];
            unsigned long long p;
            PACK2(p, lo, hi);
            if (kx < 4) { (which ? g_w2pa : g_w1pa)[g * 4 + kx] = p; }
            else        { (which ? g_w2pb : g_w1pb)[g]          = p; }
        } else if (idx < 6416) {
            int k = idx - 6400;
            int which = k >= 8;
            int p = k & 7;
            const float* bb = which ? b2 : b1;
            unsigned long long pr;
            PACK2(pr, bb[2 * p], bb[2 * p + 1]);
            (which ? g_b2p : g_b1p)[p] = pr;
        }
    }

    int pix = id & 4095;
    int oc  = (id >> 12) & 15;
    int b   = id >> 16;
    int py = pix >> 6, px = pix & 63;
    const float* xin = x + b * N_PIX;
    float acc = __ldg(bias + oc);
    #pragma unroll
    for (int ky = 0; ky < 5; ky++) {
        int gy = py + ky - 2;
        if (gy < 0 || gy >= IMG) continue;
        #pragma unroll
        for (int kx = 0; kx < 5; kx++) {
            int gx = px + kx - 2;
            if (gx < 0 || gx >= IMG) continue;
            acc = fmaf(xin[gy * IMG + gx], __ldg(w + oc * 25 + ky * 5 + kx), acc);
        }
    }
    g_buf0[id] = acc;
}

// ---------------- conv16 split: 512 threads = 4 ic-groups x (32x4 tile) ----------------
template<bool FUSE>
__global__ void __launch_bounds__(512) conv16s_kernel() {
    __shared__ __align__(16) char smraw[44032];
    float* sin_t            = (float*)smraw;                         // 18432 B
    unsigned long long* swa = (unsigned long long*)(smraw + 18432);  // 20480 B
    unsigned long long* swb = (unsigned long long*)(smraw + 38912);  //  5120 B
    unsigned long long* sred = (unsigned long long*)(smraw + 18432); // overlay

    const float* in = FUSE ? g_buf1 : g_buf0;
    const unsigned long long* gwa = FUSE ? g_w2pa : g_w1pa;
    const unsigned long long* gwb = FUSE ? g_w2pb : g_w1pb;
    const unsigned long long* gbp = FUSE ? g_b2p  : g_b1p;

    int tid  = threadIdx.x;
    int tile = blockIdx.x;
    int b    = blockIdx.y;
    int tx0  = (tile & 1) * 32;
    int ty0  = (tile >> 1) * 4;

    for (int i = tid; i < 8 * 16 * 5 * 4; i += 512) swa[i] = gwa[i];
    for (int i = tid; i < 8 * 16 * 5;     i += 512) swb[i] = gwb[i];

    const float* inb = in + b * CH * N_PIX;
    for (int idx = tid; idx < CH * 8 * 36; idx += 512) {
        int c   = idx / 288;
        int rem = idx - c * 288;
        int r   = rem / 36;
        int cc  = rem - r * 36;
        int gy = ty0 + r - 2;
        int gx = tx0 + cc - 2;
        float v = 0.f;
        if (gy >= 0 && gy < IMG && gx >= 0 && gx < IMG)
            v = inb[c * N_PIX + gy * IMG + gx];
        sin_t[idx] = v;
    }
    __syncthreads();

    int grp = tid >> 7;
    int wg  = tid & 127;
    int tx = wg & 31, ty = wg >> 5;

    unsigned long long acc[8];
    #pragma unroll
    for (int p = 0; p < 8; p++) acc[p] = 0ULL;

    #pragma unroll
    for (int icl = 0; icl < 4; icl++) {
        int ic = grp * 4 + icl;
        const float* srow = &sin_t[ic * 288 + ty * 36 + tx];
        #pragma unroll
        for (int ky = 0; ky < 5; ky++) {
            const float* rr = srow + ky * 36;
            unsigned long long pa0, pa1, pa2, pa3, pa4;
            DUP2(pa0, rr[0]); DUP2(pa1, rr[1]); DUP2(pa2, rr[2]);
            DUP2(pa3, rr[3]); DUP2(pa4, rr[4]);
            #pragma unroll
            for (int p = 0; p < 8; p++) {
                int g = (p * 16 + ic) * 5 + ky;
                const ulonglong2* wq = reinterpret_cast<const ulonglong2*>(&swa[g * 4]);
                ulonglong2 q0 = wq[0];
                ulonglong2 q1 = wq[1];
                unsigned long long w4 = swb[g];
                FMA2(acc[p], pa0, q0.x);
                FMA2(acc[p], pa1, q0.y);
                FMA2(acc[p], pa2, q1.x);
                FMA2(acc[p], pa3, q1.y);
                FMA2(acc[p], pa4, w4);
            }
        }
    }

    __syncthreads();
    if (grp > 0) {
        #pragma unroll
        for (int p = 0; p < 8; p++)
            sred[p * 384 + (grp - 1) * 128 + wg] = acc[p];
    }
    __syncthreads();

    if (grp == 0) {
        #pragma unroll
        for (int p = 0; p < 8; p++) {
            ADD2(acc[p], sred[p * 384 + wg]);
            ADD2(acc[p], sred[p * 384 + 128 + wg]);
            ADD2(acc[p], sred[p * 384 + 256 + wg]);
            ADD2(acc[p], gbp[p]);
        }

        int py = ty0 + ty, px = tx0 + tx;
        int pix = py * IMG + px;

        if (!FUSE) {
            float* outb = g_buf1 + b * CH * N_PIX + pix;
            #pragma unroll
            for (int p = 0; p < 8; p++) {
                float lo, hi;
                UNPK2(lo, hi, acc[p]);
                outb[(2 * p) * N_PIX]     = lo;
                outb[(2 * p + 1) * N_PIX] = hi;
            }
        } else {
            float v[16];
            float s = 0.f;
            #pragma unroll
            for (int p = 0; p < 8; p++) {
                UNPK2(v[2 * p], v[2 * p + 1], acc[p]);
                s += v[2 * p] + v[2 * p + 1];
            }
            float mean = s * (1.f / 16.f);
            float var = 0.f;
            float* xcb = g_xc + b * CH * N_PIX + pix;
            #pragma unroll
            for (int c = 0; c < 16; c++) {
                float d = v[c] - mean;
                var = fmaf(d, d, var);
                xcb[c * N_PIX] = d;
            }
            var *= (1.f / 15.f);
            g_invs[b * N_PIX + pix] = rsqrtf(var);
        }
    }
}

// ---------------- coupling (r4 structure, vectorized LDS mainloop) ----------------
// out[b,i,j] = (xc_i . xc_j)/16 * s_i * s_j * mask. Symmetric pairs only (tj >= ti);
// 256 threads, 4x4 per-thread tile; mirror via SMEM staging (coalesced stores).
// Mainloop: 2 LDS.128 per channel (was 6 LDS) -> 3x fewer L1 instructions.
__global__ void __launch_bounds__(256) coupling_kernel(const float* __restrict__ mask,
                                                       float* __restrict__ out) {
    __shared__ __align__(16) float sxi[16 * 64];
    __shared__ __align__(16) float sxj[16 * 64];
    __shared__ float sii[64];
    __shared__ float sij[64];
    __shared__ float stg[64 * 65];

    int b = blockIdx.x;             // batch fastest -> mask tiles reused in L2 across batches
    int p = blockIdx.y;             // 0..2079 triangular pair index (T=64)

    int ti = (int)((129.0f - sqrtf(129.0f * 129.0f - 8.0f * (float)p)) * 0.5f);
    while (((ti + 1) * 64 - ((ti + 1) * ti) / 2) <= p) ti++;
    while ((ti * 64 - (ti * (ti - 1)) / 2) > p) ti--;
    int tj = ti + (p - (ti * 64 - (ti * (ti - 1)) / 2));
    bool diag = (ti == tj);

    int tid = threadIdx.x;
    const float* xcb = g_xc + b * CH * N_PIX;

    // fill sxi/sxj (16x64 each) with float4 loads: 512 float4s over 256 threads
    #pragma unroll
    for (int it = 0; it < 2; it++) {
        int i = it * 256 + tid;           // 0..511
        int which = i >> 8;               // 0: sxi, 1: sxj
        int k = i & 255;                  // float4 index within tile
        int c = k >> 4;
        int q = k & 15;
        int t0 = which ? tj : ti;
        float4 v = *reinterpret_cast<const float4*>(xcb + c * N_PIX + t0 * 64 + q * 4);
        (which ? reinterpret_cast<float4*>(sxj) : reinterpret_cast<float4*>(sxi))[k] = v;
    }
    if (tid < 64)       sii[tid]      = g_invs[b * N_PIX + ti * 64 + tid];
    else if (tid < 128) sij[tid - 64] = g_invs[b * N_PIX + tj * 64 + tid - 64];
    __syncthreads();

    int txj = tid & 15, tyi = tid >> 4;
    int jl = txj * 4, il = tyi * 4;

    unsigned long long a0[4], a1[4];
    #pragma unroll
    for (int ii = 0; ii < 4; ii++) { a0[ii] = 0ULL; a1[ii] = 0ULL; }

    #pragma unroll
    for (int c = 0; c < 16; c++) {
        float4 av = *reinterpret_cast<const float4*>(&sxi[c * 64 + il]);       // 1 LDS.128
        ulonglong2 bq = *reinterpret_cast<const ulonglong2*>(&sxj[c * 64 + jl]); // 1 LDS.128
        unsigned long long pa;
        DUP2(pa, av.x); FMA2(a0[0], pa, bq.x); FMA2(a1[0], pa, bq.y);
        DUP2(pa, av.y); FMA2(a0[1], pa, bq.x); FMA2(a1[1], pa, bq.y);
        DUP2(pa, av.z); FMA2(a0[2], pa, bq.x); FMA2(a1[2], pa, bq.y);
        DUP2(pa, av.w); FMA2(a0[3], pa, bq.x); FMA2(a1[3], pa, bq.y);
    }

    float sj0 = sij[jl], sj1 = sij[jl + 1], sj2 = sij[jl + 2], sj3 = sij[jl + 3];
    size_t obase = (size_t)b * N_PIX * N_PIX;

    #pragma unroll
    for (int ii = 0; ii < 4; ii++) {
        float v0, v1, v2, v3;
        UNPK2(v0, v1, a0[ii]);
        UNPK2(v2, v3, a1[ii]);
        float si = sii[il + ii] * 0.0625f;     // fold /16
        v0 *= si * sj0; v1 *= si * sj1; v2 *= si * sj2; v3 *= si * sj3;

        if (!diag) {   // transposed staging for mirror write (mask not applied yet)
            stg[(jl + 0) * 65 + il + ii] = v0;
            stg[(jl + 1) * 65 + il + ii] = v1;
            stg[(jl + 2) * 65 + il + ii] = v2;
            stg[(jl + 3) * 65 + il + ii] = v3;
        }

        int ig = ti * 64 + il + ii;
        int jg = tj * 64 + jl;
        float4 m = *reinterpret_cast<const float4*>(mask + (size_t)ig * N_PIX + jg);
        STG_CS4(out + obase + (size_t)ig * N_PIX + jg,
                v0 * m.x, v1 * m.y, v2 * m.z, v3 * m.w);
    }

    if (!diag) {   // block-uniform branch -> syncthreads is safe
        __syncthreads();
        #pragma unroll
        for (int rr = 0; rr < 4; rr++) {
            int r  = il + rr;                // local j row
            int jg = tj * 64 + r;
            int c0 = jl;                     // local i col
            float s0 = stg[r * 65 + c0 + 0];
            float s1 = stg[r * 65 + c0 + 1];
            float s2 = stg[r * 65 + c0 + 2];
            float s3 = stg[r * 65 + c0 + 3];
            float4 m = *reinterpret_cast<const float4*>(mask + (size_t)jg * N_PIX + ti * 64 + c0);
            STG_CS4(out + obase + (size_t)jg * N_PIX + ti * 64 + c0,
                    s0 * m.x, s1 * m.y, s2 * m.z, s3 * m.w);
        }
    }
}

// ---------------- launch ----------------
extern "C" void kernel_launch(void* const* d_in, const int* in_sizes, int n_in,
                              void* d_out, int out_size) {
    const float* x    = (const float*)d_in[0];
    const float* w0   = (const float*)d_in[1];
    const float* b0   = (const float*)d_in[2];
    const float* w1   = (const float*)d_in[3];
    const float* b1   = (const float*)d_in[4];
    const float* w2   = (const float*)d_in[5];
    const float* b2   = (const float*)d_in[6];
    const float* mask = (const float*)d_in[7];
    float* out = (float*)d_out;

    conv0_kernel<<<(B * CH * N_PIX) / 256, 256>>>(x, w0, b0, w1, b1, w2, b2);
    conv16s_kernel<false><<<dim3(32, B), 512>>>();      // g_buf0 -> g_buf1
    conv16s_kernel<true ><<<dim3(32, B), 512>>>();      // g_buf1 -> g_xc, g_invs
    coupling_kernel<<<dim3(B, 2080), 256>>>(mask, out); // -> d_out
}